// round 15
// baseline (speedup 1.0000x reference)
#include <cuda_runtime.h>
#include <cuda_bf16.h>
#include <cuda_fp16.h>
#include <cstdint>

#define NTOK 16384
#define MD   2048
#define PD   256
#define NE   64
#define BK   32
#define BM   64

// ---------------- device globals ----------------
__device__ __align__(16) __half g_Wh[PD * MD];
__device__ __align__(16) __nv_bfloat16 g_simHi[NE * PD];
__device__ __align__(16) __nv_bfloat16 g_simLo[NE * PD];
__device__ float g_scale;
__device__ float g_active;

// ---------------- helpers ----------------
__device__ __forceinline__ uint32_t smem_u32(const void* p) {
    uint32_t a;
    asm("{ .reg .u64 t; cvta.to.shared.u64 t, %1; cvt.u32.u64 %0, t; }" : "=r"(a) : "l"(p));
    return a;
}
#define LDSM4(r0, r1, r2, r3, a)                                                  \
    asm volatile("ldmatrix.sync.aligned.m8n8.x4.shared.b16 {%0,%1,%2,%3}, [%4];" \
                 : "=r"(r0), "=r"(r1), "=r"(r2), "=r"(r3) : "r"(a))
#define MMAB16(c, a, b)                                                           \
    asm volatile("mma.sync.aligned.m16n8k16.row.col.f32.bf16.bf16.f32 "           \
                 "{%0,%1,%2,%3}, {%4,%5,%6,%7}, {%8,%9}, {%0,%1,%2,%3};"          \
                 : "+f"((c)[0]), "+f"((c)[1]), "+f"((c)[2]), "+f"((c)[3])         \
                 : "r"((a)[0]), "r"((a)[1]), "r"((a)[2]), "r"((a)[3]),            \
                   "r"((b)[0]), "r"((b)[1]))
#define MMAF16(c, a, b)                                                           \
    asm volatile("mma.sync.aligned.m16n8k16.row.col.f32.f16.f16.f32 "             \
                 "{%0,%1,%2,%3}, {%4,%5,%6,%7}, {%8,%9}, {%0,%1,%2,%3};"          \
                 : "+f"((c)[0]), "+f"((c)[1]), "+f"((c)[2]), "+f"((c)[3])         \
                 : "r"((a)[0]), "r"((a)[1]), "r"((a)[2]), "r"((a)[3]),            \
                   "r"((b)[0]), "r"((b)[1]))
#define CP16(dst, src) asm volatile("cp.async.cg.shared.global [%0], [%1], 16;" :: "r"(dst), "l"(src))
#define CP_COMMIT()    asm volatile("cp.async.commit_group;" ::: "memory")
#define CP_WAIT0()     asm volatile("cp.async.wait_group 0;" ::: "memory")

__device__ __forceinline__ uint32_t pack_h2(float a, float b) {
    __half2 t = __floats2half2_rn(a, b);
    return *reinterpret_cast<uint32_t*>(&t);
}
__device__ __forceinline__ uint32_t pack_hi(float v0, float v1, float& l0, float& l1) {
    __nv_bfloat16 h0 = __float2bfloat16(v0), h1 = __float2bfloat16(v1);
    l0 = v0 - __bfloat162float(h0);
    l1 = v1 - __bfloat162float(h1);
    return (uint32_t)__bfloat16_as_ushort(h0) | ((uint32_t)__bfloat16_as_ushort(h1) << 16);
}
__device__ __forceinline__ uint32_t pack_bf2(float v0, float v1) {
    return (uint32_t)__bfloat16_as_ushort(__float2bfloat16(v0)) |
           ((uint32_t)__bfloat16_as_ushort(__float2bfloat16(v1)) << 16);
}

// ---------------- prep: W convert (blocks 0..511) + sim normalize (blocks 512..519) ----
__global__ void prep_all_kernel(const float* __restrict__ W,
                                const float* __restrict__ sim,
                                const float* __restrict__ temperature,
                                const float* __restrict__ mask) {
    if (blockIdx.x < 512) {
        int i = blockIdx.x * 256 + threadIdx.x;
        float4 v = ((const float4*)W)[i];
        ((uint2*)g_Wh)[i] = make_uint2(pack_h2(v.x, v.y), pack_h2(v.z, v.w));
        return;
    }
    int wg = (blockIdx.x - 512) * 8 + (threadIdx.x >> 5);   // expert 0..63
    int lane = threadIdx.x & 31;
    float vals[8];
    float ss = 0.f;
    #pragma unroll
    for (int j = 0; j < 8; j++) {
        float v = sim[(lane + 32 * j) * NE + wg];
        vals[j] = v;
        ss += v * v;
    }
    #pragma unroll
    for (int o = 16; o > 0; o >>= 1) ss += __shfl_xor_sync(0xffffffffu, ss, o);
    float inv = 1.f / fmaxf(sqrtf(ss), 1e-12f);
    #pragma unroll
    for (int j = 0; j < 8; j++) {
        float v = vals[j] * inv;
        __nv_bfloat16 h = __float2bfloat16(v);
        g_simHi[wg * PD + lane + 32 * j] = h;
        g_simLo[wg * PD + lane + 32 * j] = __float2bfloat16(v - __bfloat162float(h));
    }
    if (blockIdx.x == 512 && threadIdx.x == 0) {
        float a = 0.f;
        for (int i = 0; i < NE; i++) a += mask[i];
        g_active = a;
        g_scale = expf(fminf(temperature[0], 4.6051701859880913680f));
    }
}

// ---------------- smem layout (bytes) ----------------
// mainloop: 2 stages of (A 5120 | B 20480) = 25600 each
#define G1_A 0
#define G1_B 5120
#define G1_STAGE 25600
// tail overlay:
#define SHI_B   0          // 64 x 264 elems x 2B = 33792
#define SLO_B   33792
#define CBUF_B  67584      // 64 x 68 f32 = 17408
#define SCBUF_B 84992      // 64 x 68 f32 = 17408 (end 102400)
#define BIAS_B  102400     // 256 f32
#define MASK_B  103424     // 64 f32
#define NORM_B  103680     // 64 x 2 f32
#define SINV_B  104192     // 64 f32
#define SMEM_TOTAL 104448

// ---------------- fused kernel ----------------
__global__ void __launch_bounds__(256, 2)
fused_kernel(const float* __restrict__ X, const float* __restrict__ bias,
             const float* __restrict__ mask,
             float* __restrict__ out_logits, float* __restrict__ out_topk,
             int write_topk) {
    extern __shared__ __align__(16) char dsm[];
    const uint32_t sb = smem_u32(dsm);

    const int tid = threadIdx.x;
    const int wid = tid >> 5, lane = tid & 31;
    const int warpM = wid & 3;    // 4 x 16 rows
    const int warpN = wid >> 2;   // 2 x 128 cols
    const int by = blockIdx.x;
    const int tokBase = by * BM;

    const uint32_t aRow  = (uint32_t)(lane & 15);
    const uint32_t aByte = (uint32_t)((lane >> 4) * 16);
    const int gq = lane >> 3;
    const uint32_t bRowBase = (uint32_t)(((gq >> 1) << 3) + (lane & 7));
    const uint32_t bByte = (uint32_t)((gq & 1) * 16);

    const int aRowL = tid >> 3, aC4 = (tid & 7) * 4;   // A: idx=i*256+tid, i<2
    const int bRowL = tid >> 2, bC8 = (tid & 3) * 8;   // B: + i*64, i<4

    float acc[16][4];
    #pragma unroll
    for (int j = 0; j < 16; j++)
        #pragma unroll
        for (int q = 0; q < 4; q++) acc[j][q] = 0.f;

    const float* Xb = X + (size_t)by * BM * MD;

    // prologue: A(0) load+convert+STS; cp.async B(0) -> stage 0
    float4 aReg[2];
    #pragma unroll
    for (int i = 0; i < 2; i++) {
        int idx = i * 256 + tid;
        aReg[i] = *(const float4*)(Xb + (size_t)(idx >> 3) * MD + (idx & 7) * 4);
    }
    #pragma unroll
    for (int i = 0; i < 2; i++) {
        int idx = i * 256 + tid;
        int row = idx >> 3, c4 = (idx & 7) * 4;
        *(uint2*)(dsm + G1_A + row * 80 + c4 * 2) =
            make_uint2(pack_h2(aReg[i].x, aReg[i].y), pack_h2(aReg[i].z, aReg[i].w));
    }
    #pragma unroll
    for (int i = 0; i < 4; i++) {
        int row = bRowL + i * 64;
        CP16(sb + G1_B + (uint32_t)(row * 80 + bC8 * 2), g_Wh + (size_t)row * MD + bC8);
    }
    CP_COMMIT();

    // ================= mainloop: single-term fp16, convert hidden under MMA ====
    for (int kc = 0; kc < MD / BK; kc++) {
        const int s = kc & 1;
        const uint32_t stu = sb + s * G1_STAGE;
        char* stn = dsm + (s ^ 1) * G1_STAGE;
        const bool nxt = (kc + 1 < MD / BK);

        CP_WAIT0();
        __syncthreads();

        if (nxt) {
            const int k0n = (kc + 1) * BK;
            #pragma unroll
            for (int i = 0; i < 4; i++) {
                int row = bRowL + i * 64;
                CP16(sb + (s ^ 1) * G1_STAGE + G1_B + (uint32_t)(row * 80 + bC8 * 2),
                     g_Wh + (size_t)row * MD + k0n + bC8);
            }
            CP_COMMIT();
            #pragma unroll
            for (int i = 0; i < 2; i++) {
                int idx = i * 256 + tid;
                aReg[i] = *(const float4*)(Xb + (size_t)(idx >> 3) * MD + k0n + (idx & 7) * 4);
            }
        }

        #pragma unroll
        for (int ks = 0; ks < 2; ks++) {
            uint32_t af[4];
            uint32_t aoff = (uint32_t)((warpM * 16 + aRow) * 80) +
                            (uint32_t)(ks * 32) + aByte;
            LDSM4(af[0], af[1], af[2], af[3], stu + G1_A + aoff);
            #pragma unroll
            for (int p = 0; p < 4; p++) {
                uint32_t bf[2][4];
                #pragma unroll
                for (int j = 0; j < 2; j++) {
                    int nf2 = p * 2 + j;
                    uint32_t off = (uint32_t)((warpN * 128 + nf2 * 16 + bRowBase) * 80) +
                                   (uint32_t)(ks * 32) + bByte;
                    LDSM4(bf[j][0], bf[j][1], bf[j][2], bf[j][3], stu + G1_B + off);
                }
                #pragma unroll
                for (int j = 0; j < 2; j++)
                    #pragma unroll
                    for (int half = 0; half < 2; half++) {
                        int nf = (p * 2 + j) * 2 + half;
                        uint32_t b2[2] = { bf[j][half * 2], bf[j][half * 2 + 1] };
                        MMAF16(acc[nf], af, b2);
                    }
                // interleave next-A convert+STS (2 chunks at p==0 and p==2)
                if (ks == 1 && nxt && (p & 1) == 0) {
                    int i = p >> 1;
                    int idx = i * 256 + tid;
                    int row = idx >> 3, c4 = (idx & 7) * 4;
                    *(uint2*)(stn + G1_A + row * 80 + c4 * 2) =
                        make_uint2(pack_h2(aReg[i].x, aReg[i].y),
                                   pack_h2(aReg[i].z, aReg[i].w));
                }
            }
        }
    }

    // ================= fused tail (bf16 3-term GEMM2) ======
    __syncthreads();

    #pragma unroll
    for (int i = 0; i < 8; i++) {
        int idx = i * 256 + tid;
        int row = idx >> 5, c8 = (idx & 31) * 8;
        *(uint4*)(dsm + SHI_B + row * 528 + c8 * 2) = *(const uint4*)(g_simHi + row * PD + c8);
        *(uint4*)(dsm + SLO_B + row * 528 + c8 * 2) = *(const uint4*)(g_simLo + row * PD + c8);
    }
    ((float*)(dsm + BIAS_B))[tid] = bias[tid];
    if (tid < NE) ((float*)(dsm + MASK_B))[tid] = mask[tid];
    __syncthreads();

    const float* sBias = (const float*)(dsm + BIAS_B);
    const int qr = lane >> 2, qc = (lane & 3) * 2;
    float ss0 = 0.f, ss1 = 0.f;
    #pragma unroll
    for (int nf = 0; nf < 16; nf++) {
        int c = warpN * 128 + nf * 8 + qc;
        float b0 = sBias[c], b1 = sBias[c + 1];
        acc[nf][0] += b0; acc[nf][1] += b1;
        acc[nf][2] += b0; acc[nf][3] += b1;
        ss0 += acc[nf][0] * acc[nf][0] + acc[nf][1] * acc[nf][1];
        ss1 += acc[nf][2] * acc[nf][2] + acc[nf][3] * acc[nf][3];
    }
    ss0 += __shfl_xor_sync(0xffffffffu, ss0, 1);
    ss0 += __shfl_xor_sync(0xffffffffu, ss0, 2);
    ss1 += __shfl_xor_sync(0xffffffffu, ss1, 1);
    ss1 += __shfl_xor_sync(0xffffffffu, ss1, 2);
    if ((lane & 3) == 0) {
        int r0 = warpM * 16 + qr;
        ((float*)(dsm + NORM_B))[r0 * 2 + warpN]       = ss0;
        ((float*)(dsm + NORM_B))[(r0 + 8) * 2 + warpN] = ss1;
    }
    __syncthreads();
    if (tid < BM) {
        const float* nb = (const float*)(dsm + NORM_B);
        float tot = nb[tid * 2] + nb[tid * 2 + 1];
        ((float*)(dsm + SINV_B))[tid] = g_scale / fmaxf(sqrtf(tot), 1e-12f);
    }
    __syncthreads();

    float acc2[8][4];
    #pragma unroll
    for (int j = 0; j < 8; j++)
        #pragma unroll
        for (int q = 0; q < 4; q++) acc2[j][q] = 0.f;

    #pragma unroll
    for (int ks = 0; ks < 8; ks++) {
        uint32_t ahi[4], alo[4];
        float l0, l1;
        ahi[0] = pack_hi(acc[2 * ks][0],     acc[2 * ks][1],     l0, l1); alo[0] = pack_bf2(l0, l1);
        ahi[1] = pack_hi(acc[2 * ks][2],     acc[2 * ks][3],     l0, l1); alo[1] = pack_bf2(l0, l1);
        ahi[2] = pack_hi(acc[2 * ks + 1][0], acc[2 * ks + 1][1], l0, l1); alo[2] = pack_bf2(l0, l1);
        ahi[3] = pack_hi(acc[2 * ks + 1][2], acc[2 * ks + 1][3], l0, l1); alo[3] = pack_bf2(l0, l1);
        #pragma unroll
        for (int ne2 = 0; ne2 < 4; ne2++) {
            uint32_t boff = (uint32_t)((ne2 * 16 + bRowBase) * 528) +
                            (uint32_t)((warpN * 8 + ks) * 32) + bByte;
            uint32_t bh[4], bl[4];
            LDSM4(bh[0], bh[1], bh[2], bh[3], sb + SHI_B + boff);
            LDSM4(bl[0], bl[1], bl[2], bl[3], sb + SLO_B + boff);
            #pragma unroll
            for (int half = 0; half < 2; half++) {
                uint32_t b2[2] = { bh[half * 2], bh[half * 2 + 1] };
                MMAB16(acc2[ne2 * 2 + half], ahi, b2);
            }
            #pragma unroll
            for (int half = 0; half < 2; half++) {
                uint32_t b2[2] = { bl[half * 2], bl[half * 2 + 1] };
                MMAB16(acc2[ne2 * 2 + half], ahi, b2);
            }
            #pragma unroll
            for (int half = 0; half < 2; half++) {
                uint32_t b2[2] = { bh[half * 2], bh[half * 2 + 1] };
                MMAB16(acc2[ne2 * 2 + half], alo, b2);
            }
        }
    }

    if (warpN == 1) {
        float* cb = (float*)(dsm + CBUF_B);
        #pragma unroll
        for (int nf = 0; nf < 8; nf++) {
            int r = warpM * 16 + qr;
            int c = nf * 8 + qc;
            *(float2*)(cb + r * 68 + c)       = make_float2(acc2[nf][0], acc2[nf][1]);
            *(float2*)(cb + (r + 8) * 68 + c) = make_float2(acc2[nf][2], acc2[nf][3]);
        }
    }
    __syncthreads();

    if (warpN == 0) {
        const float* cb = (const float*)(dsm + CBUF_B);
        const float* sInv = (const float*)(dsm + SINV_B);
        const float* sMask = (const float*)(dsm + MASK_B);
        float* sc = (float*)(dsm + SCBUF_B);
        int r0 = warpM * 16 + qr, r1 = r0 + 8;
        float inv0 = sInv[r0], inv1 = sInv[r1];
        float p0[16], p1[16];
        #pragma unroll
        for (int nf = 0; nf < 8; nf++) {
            int c = nf * 8 + qc;
            float2 c0 = *(const float2*)(cb + r0 * 68 + c);
            float2 c1 = *(const float2*)(cb + r1 * 68 + c);
            bool m0 = sMask[c] == 0.f, m1 = sMask[c + 1] == 0.f;
            float a  = m0 ? -1e9f : (acc2[nf][0] + c0.x) * inv0;
            float b  = m1 ? -1e9f : (acc2[nf][1] + c0.y) * inv0;
            float cc = m0 ? -1e9f : (acc2[nf][2] + c1.x) * inv1;
            float dd = m1 ? -1e9f : (acc2[nf][3] + c1.y) * inv1;
            p0[nf * 2] = a;  p0[nf * 2 + 1] = b;
            p1[nf * 2] = cc; p1[nf * 2 + 1] = dd;
            *(float2*)(out_logits + (size_t)(tokBase + r0) * NE + c) = make_float2(a, b);
            *(float2*)(out_logits + (size_t)(tokBase + r1) * NE + c) = make_float2(cc, dd);
        }
        if (write_topk) {
            float m0 = -1e30f, m1 = -1e30f;
            #pragma unroll
            for (int j = 0; j < 16; j++) { m0 = fmaxf(m0, p0[j]); m1 = fmaxf(m1, p1[j]); }
            #pragma unroll
            for (int o = 1; o < 4; o <<= 1) {
                m0 = fmaxf(m0, __shfl_xor_sync(0xffffffffu, m0, o));
                m1 = fmaxf(m1, __shfl_xor_sync(0xffffffffu, m1, o));
            }
            float s0 = 0.f, s1 = 0.f;
            #pragma unroll
            for (int j = 0; j < 16; j++) {
                p0[j] = __expf(p0[j] - m0); s0 += p0[j];
                p1[j] = __expf(p1[j] - m1); s1 += p1[j];
            }
            #pragma unroll
            for (int o = 1; o < 4; o <<= 1) {
                s0 += __shfl_xor_sync(0xffffffffu, s0, o);
                s1 += __shfl_xor_sync(0xffffffffu, s1, o);
            }
            float is0 = 1.f / s0, is1 = 1.f / s1;
            #pragma unroll
            for (int nf = 0; nf < 8; nf++) {
                int c = nf * 8 + qc;
                *(float2*)(sc + r0 * 68 + c) =
                    make_float2(p0[nf * 2] * is0 + 1e-14f, p0[nf * 2 + 1] * is0 + 1e-14f);
                *(float2*)(sc + r1 * 68 + c) =
                    make_float2(p1[nf * 2] * is1 + 1e-14f, p1[nf * 2 + 1] * is1 + 1e-14f);
            }
        }
    }
    __syncthreads();

    if (write_topk && tid < BM) {
        const float* row = (const float*)(dsm + SCBUF_B) + tid * 68;
        float v[64];
        #pragma unroll
        for (int i = 0; i < 16; i++)
            *(float4*)(v + i * 4) = *(const float4*)(row + i * 4);
        #pragma unroll
        for (int k = 2; k <= 64; k <<= 1)
            #pragma unroll
            for (int j = k >> 1; j > 0; j >>= 1)
                #pragma unroll
                for (int i = 0; i < 64; i++) {
                    int p = i ^ j;
                    if (p > i) {
                        bool up = ((i & k) == 0);
                        float a = v[i], b = v[p];
                        bool sw = up ? (a > b) : (a < b);
                        float lo = sw ? b : a, hi = sw ? a : b;
                        v[i] = lo; v[p] = hi;
                    }
                }
        float cum = 0.f; int k = 0;
        #pragma unroll
        for (int r = 63; r >= 0; r--) { if (cum < 1.f) k++; cum += v[r]; }
        out_topk[tokBase + tid] = fminf((float)k, g_active);
    }
}

// ---------------- launch ----------------
extern "C" void kernel_launch(void* const* d_in, const int* in_sizes, int n_in,
                              void* d_out, int out_size) {
    const float* x    = (const float*)d_in[0];
    const float* W    = (const float*)d_in[1];
    const float* b    = (const float*)d_in[2];
    const float* sim  = (const float*)d_in[3];
    const float* temp = (const float*)d_in[4];
    const float* mask = (const float*)d_in[5];
    float* out = (float*)d_out;

    cudaFuncSetAttribute(fused_kernel, cudaFuncAttributeMaxDynamicSharedMemorySize, SMEM_TOTAL);

    prep_all_kernel<<<520, 256>>>(W, sim, temp, mask);

    const int logits_elems = NTOK * NE;
    int write_topk = (out_size >= logits_elems + NTOK) ? 1 : 0;
    fused_kernel<<<NTOK / BM, 256, SMEM_TOTAL>>>(x, b, mask, out, out + logits_elems, write_topk);
}